// round 15
// baseline (speedup 1.0000x reference)
#include <cuda_runtime.h>
#include <cuda_fp16.h>
#include <cstdint>

// ---------------------------------------------------------------------------
// HyperConv via warp-level mma.sync fp16 m16n8k16 (compute_103-safe).
//   out[b,c,f] = sum_{k=1..4095} x[b,c,k] * W[b,k-1,f] + bias[b,c,f]
//   W    = conv2(relu(conv1(z,ww1)+wb1), ww2)+wb2   (T=4096 steps)
//   bias = same with bw*/bb*, only first 512 steps needed
// R14: BK 32->64 (4x fewer iterations), single __syncthreads per iteration
// (wait -> barrier -> load(i+1) -> compute; WAR-safe by barrier placement).
// ---------------------------------------------------------------------------

namespace {
constexpr int BATCH = 8;
constexpr int TT    = 4096;
constexpr int TZv   = 4098;
constexpr int ZD    = 128;
constexpr int FF    = 512;
constexpr int T1W   = 4097;   // hidden steps, weights path
constexpr int T1B   = 513;    // hidden steps, bias path

constexpr int BM = 128, BN = 128, BK = 64;
constexpr int APADH = 72;                // A row stride (halves): 144B -> ldmatrix conflict-free
constexpr int BPADH = 136;               // B row stride (halves): 272B -> ldmatrix conflict-free
constexpr int AS_H = BM * APADH;         // 9216 halves
constexpr int BS_H = BK * BPADH;         // 8704 halves
constexpr int STG_H = AS_H + BS_H;       // 17920 halves = 35840 B / stage
constexpr int SMEM_BYTES = 2 * STG_H * 2;   // 71680 B (2 CTAs/SM)
}

// Scratch (device globals; no allocations allowed). fp16 operand buffers.
__device__ __align__(256) __half g_h1w[BATCH * T1W * FF];   // ~33.5 MB
__device__ __align__(256) __half g_h1b[BATCH * T1B * FF];   // ~4.2 MB
__device__ __align__(256) __half g_wts[BATCH * TT  * FF];   // ~33.5 MB
__device__ __align__(256) float  g_bias[BATCH * 512 * FF];  // ~8.4 MB (fp32, add-only)
__device__ __align__(256) __half g_xh [BATCH * 512 * TT];   // ~33.5 MB
__device__ __align__(256) __half g_zh [BATCH * TZv * ZD];   // ~8.4 MB
__device__ __align__(256) __half g_ww1h[2 * ZD * FF];
__device__ __align__(256) __half g_ww2h[2 * FF * FF];
__device__ __align__(256) __half g_bw1h[2 * ZD * FF];
__device__ __align__(256) __half g_bw2h[2 * FF * FF];

#define DI __device__ __forceinline__

DI uint32_t smem_u32(const void* p) {
    uint32_t a;
    asm("{ .reg .u64 t; cvta.to.shared.u64 t, %1; cvt.u32.u64 %0, t; }"
        : "=r"(a) : "l"(p));
    return a;
}
DI void cp16(uint32_t dst, const void* src) {
    asm volatile("cp.async.cg.shared.global [%0], [%1], 16;"
                 :: "r"(dst), "l"(src));
}
DI void cp16z(uint32_t dst, const void* src, int valid) {  // zero-fill if !valid
    asm volatile("cp.async.cg.shared.global [%0], [%1], 16, %2;"
                 :: "r"(dst), "l"(src), "r"(valid ? 16 : 0));
}
DI void cp_commit() { asm volatile("cp.async.commit_group;"); }
DI void cp_wait0()  { asm volatile("cp.async.wait_group 0;"); }

DI void ldsm_x4(uint32_t& r0, uint32_t& r1, uint32_t& r2, uint32_t& r3, uint32_t a) {
    asm volatile("ldmatrix.sync.aligned.m8n8.x4.shared.b16 {%0,%1,%2,%3}, [%4];"
                 : "=r"(r0), "=r"(r1), "=r"(r2), "=r"(r3) : "r"(a));
}
DI void ldsm_x4t(uint32_t& r0, uint32_t& r1, uint32_t& r2, uint32_t& r3, uint32_t a) {
    asm volatile("ldmatrix.sync.aligned.m8n8.x4.trans.shared.b16 {%0,%1,%2,%3}, [%4];"
                 : "=r"(r0), "=r"(r1), "=r"(r2), "=r"(r3) : "r"(a));
}
DI void mma16(float c[4], const uint32_t a[4], uint32_t b0, uint32_t b1) {
    asm volatile(
        "mma.sync.aligned.m16n8k16.row.col.f32.f16.f16.f32 "
        "{%0,%1,%2,%3}, {%4,%5,%6,%7}, {%8,%9}, {%0,%1,%2,%3};"
        : "+f"(c[0]), "+f"(c[1]), "+f"(c[2]), "+f"(c[3])
        : "r"(a[0]), "r"(a[1]), "r"(a[2]), "r"(a[3]), "r"(b0), "r"(b1));
}

// Per-lane ldmatrix base offsets (bytes) within a stage.
// A [m][k] halves, row stride APADH. x4: lanes 0-7 rows m+0..7 @k0,
// 8-15 rows m+8..15 @k0, 16-23 rows m+0..7 @k+8, 24-31 rows m+8..15 @k+8.
DI uint32_t a_lane_base(int lane, int wm) {
    int row = wm + (lane & 7) + ((lane >> 3) & 1) * 8;
    int col = ((lane >> 4) & 1) * 8;
    return (uint32_t)(row * APADH + col) * 2u;
}
// B [k][n] halves, row stride BPADH. x4.trans: lanes 0-7 rows k+0..7 @n0,
// 8-15 rows k+8..15 @n0, 16-23 rows k+0..7 @n+8, 24-31 rows k+8..15 @n+8.
DI uint32_t b_lane_base(int lane, int wn) {
    int row = (lane & 7) + ((lane >> 3) & 1) * 8;
    int col = wn + ((lane >> 4) & 1) * 8;
    return (uint32_t)(row * BPADH + col) * 2u;
}

// Load fragments for one k16 step (ks in 0..3 within a BK=64 chunk).
DI void load_frags(uint32_t a_sb, uint32_t b_sb, int ks,
                   uint32_t af[4][4], uint32_t bq[2][4]) {
    const uint32_t ak = a_sb + (uint32_t)(ks * 16) * 2u;
    const uint32_t bk = b_sb + (uint32_t)(ks * 16 * BPADH) * 2u;
#pragma unroll
    for (int mf = 0; mf < 4; mf++)
        ldsm_x4(af[mf][0], af[mf][1], af[mf][2], af[mf][3],
                ak + (uint32_t)(mf * 16 * APADH) * 2u);
#pragma unroll
    for (int nfp = 0; nfp < 2; nfp++)
        ldsm_x4t(bq[nfp][0], bq[nfp][1], bq[nfp][2], bq[nfp][3],
                 bk + (uint32_t)(nfp * 16) * 2u);
}

// One BK=64 chunk: 4 k16 steps, double-buffered fragments.
DI void compute_chunk(uint32_t a_sb, uint32_t b_sb, float acc[4][4][4]) {
    uint32_t af[2][4][4], bq[2][2][4];
    load_frags(a_sb, b_sb, 0, af[0], bq[0]);
#pragma unroll
    for (int ks = 0; ks < 4; ks++) {
        const int cur = ks & 1;
        if (ks < 3) load_frags(a_sb, b_sb, ks + 1, af[cur ^ 1], bq[cur ^ 1]);
#pragma unroll
        for (int mf = 0; mf < 4; mf++)
#pragma unroll
            for (int nf = 0; nf < 4; nf++)
                mma16(acc[mf][nf], af[cur][mf],
                      bq[cur][nf >> 1][(nf & 1) * 2],
                      bq[cur][nf >> 1][(nf & 1) * 2 + 1]);
    }
}

// Elementwise fp32 -> fp16 converter (grid-stride, float4 -> half4).
__global__ void cvt_f16_kernel(const float4* __restrict__ in,
                               uint2* __restrict__ out, int n4) {
    for (int i = blockIdx.x * blockDim.x + threadIdx.x; i < n4;
         i += gridDim.x * blockDim.x) {
        float4 v = in[i];
        __half2 lo = __floats2half2_rn(v.x, v.y);
        __half2 hi = __floats2half2_rn(v.z, v.w);
        uint2 o;
        o.x = *(uint32_t*)&lo; o.y = *(uint32_t*)&hi;
        out[i] = o;
    }
}

// ---------------------------------------------------------------------------
// mma_gemm: C[m, n0:n0+128] = A_row(m)[0:K] @ W[K,512] + biasVec
// A_row(m) = A + b*batchStride + t*rowStride (halves), m = b*rowsPerBatch + t.
// OUTH: write fp16; else fp32.
// ---------------------------------------------------------------------------
template<bool RELU, bool OUTH>
__global__ void __launch_bounds__(256, 2) mma_gemm(
    const __half* __restrict__ A, int rowsPerBatch, int rowStride, long batchStride,
    const __half* __restrict__ W, int K,
    const float* __restrict__ biasVec, void* __restrict__ Cv, int M)
{
    extern __shared__ __half smh[];
    const uint32_t sb = smem_u32(smh);
    const int tid = threadIdx.x, lane = tid & 31, wid = tid >> 5;
    const int m0 = blockIdx.y * BM, n0 = blockIdx.x * BN;

    // A gmem mapping: row am = tid>>1 (0..127), half-chunk ah = (tid&1)*32 halves
    const int am = tid >> 1, ah = (tid & 1) * 32;
    const __half* aptr;
    {
        int mm = m0 + am; if (mm >= M) mm = M - 1;   // clamp; store guarded
        int b = mm / rowsPerBatch, t = mm - b * rowsPerBatch;
        aptr = A + (long)b * batchStride + (long)t * rowStride + ah;
    }
    const uint32_t adst0 = sb + (uint32_t)(am * APADH + ah) * 2u;

    // B gmem mapping: k-row bk = tid>>2 (0..63), n-chunk bn = (tid&3)*32 halves
    const int bk = tid >> 2, bn = (tid & 3) * 32;
    const __half* bptr = W + (long)bk * FF + n0 + bn;
    const uint32_t bdst0 = sb + (uint32_t)(AS_H + bk * BPADH + bn) * 2u;

    const int NC = K / BK;

#define LOAD_STAGE(i)                                                          \
    do {                                                                       \
        const uint32_t off = (uint32_t)(((i) & 1) * STG_H) * 2u;               \
        const __half* asrc = aptr + (i) * BK;                                  \
        cp16(adst0 + off,      asrc);                                          \
        cp16(adst0 + off + 16, asrc + 8);                                      \
        cp16(adst0 + off + 32, asrc + 16);                                     \
        cp16(adst0 + off + 48, asrc + 24);                                     \
        const __half* bsrc = bptr + (long)(i) * BK * FF;                       \
        cp16(bdst0 + off,      bsrc);                                          \
        cp16(bdst0 + off + 16, bsrc + 8);                                      \
        cp16(bdst0 + off + 32, bsrc + 16);                                     \
        cp16(bdst0 + off + 48, bsrc + 24);                                     \
        cp_commit();                                                           \
    } while (0)

    float acc[4][4][4];
#pragma unroll
    for (int a = 0; a < 4; a++)
#pragma unroll
        for (int b = 0; b < 4; b++)
#pragma unroll
            for (int c = 0; c < 4; c++) acc[a][b][c] = 0.f;

    const int wm = (wid & 1) * 64, wn = (wid >> 1) * 32;
    const int g = lane >> 2, t4 = lane & 3;
    const uint32_t abase = a_lane_base(lane, wm);
    const uint32_t bbase = b_lane_base(lane, wn) + (uint32_t)AS_H * 2u;

    LOAD_STAGE(0);

    for (int i = 0; i < NC; i++) {
        cp_wait0();                 // stage i fully in SMEM
        __syncthreads();            // all warps done with buffer (i-1)&1
        if (i + 1 < NC) LOAD_STAGE(i + 1);   // overwrites (i+1)&1 = (i-1)&1: safe
        const uint32_t soff = sb + (uint32_t)((i & 1) * STG_H) * 2u;
        compute_chunk(soff + abase, soff + bbase, acc);
    }
#undef LOAD_STAGE

    // epilogue (c frag: m = g(+8), n = t4*2(+1))
    float bv[4][2];
#pragma unroll
    for (int nf = 0; nf < 4; nf++) {
        int nc = n0 + wn + nf * 8 + t4 * 2;
        bv[nf][0] = biasVec[nc]; bv[nf][1] = biasVec[nc + 1];
    }
#pragma unroll
    for (int mf = 0; mf < 4; mf++)
#pragma unroll
        for (int hh = 0; hh < 2; hh++) {
            int m = m0 + wm + mf * 16 + g + hh * 8;
            if (m < M) {
#pragma unroll
                for (int nf = 0; nf < 4; nf++) {
                    float vx = acc[mf][nf][hh * 2 + 0] + bv[nf][0];
                    float vy = acc[mf][nf][hh * 2 + 1] + bv[nf][1];
                    if (RELU) { vx = fmaxf(vx, 0.f); vy = fmaxf(vy, 0.f); }
                    long idx = (long)m * FF + n0 + wn + nf * 8 + t4 * 2;
                    if (OUTH) {
                        __half2 h = __floats2half2_rn(vx, vy);
                        *(__half2*)((__half*)Cv + idx) = h;
                    } else {
                        float2 v; v.x = vx; v.y = vy;
                        *(float2*)((float*)Cv + idx) = v;
                    }
                }
            }
        }
}

// ---------------------------------------------------------------------------
// mma_final: out[b,m,n] = sum_{k=1..4095} x[b,m,k]*wts[b,k-1,n] + biasM[b,m,n]
// A = fp16 x, B row kg reads wts[kg-1]; kg==0 zero-filled.
// grid = (4 n-tiles, 4 m-tiles, 8 batches), K=4096 -> 64 chunks.
// ---------------------------------------------------------------------------
__global__ void __launch_bounds__(256, 2) mma_final(
    const __half* __restrict__ x, const __half* __restrict__ wts,
    const float* __restrict__ biasM, float* __restrict__ out)
{
    extern __shared__ __half smh[];
    const uint32_t sb = smem_u32(smh);
    const int tid = threadIdx.x, lane = tid & 31, wid = tid >> 5;
    const int bz = blockIdx.z;
    const int m0 = blockIdx.y * BM, n0 = blockIdx.x * BN;

    const int am = tid >> 1, ah = (tid & 1) * 32;
    const __half* aptr = x + (long)(bz * 512 + m0 + am) * TT + ah;
    const uint32_t adst0 = sb + (uint32_t)(am * APADH + ah) * 2u;

    const int bk = tid >> 2, bn = (tid & 3) * 32;
    const __half* wb = wts + (long)bz * TT * FF + n0 + bn;
    const uint32_t bdst0 = sb + (uint32_t)(AS_H + bk * BPADH + bn) * 2u;

    const int NC = TT / BK;   // 64

#define LOAD_STAGE_F(i)                                                        \
    do {                                                                       \
        const uint32_t off = (uint32_t)(((i) & 1) * STG_H) * 2u;               \
        const __half* asrc = aptr + (i) * BK;                                  \
        cp16(adst0 + off,      asrc);                                          \
        cp16(adst0 + off + 16, asrc + 8);                                      \
        cp16(adst0 + off + 32, asrc + 16);                                     \
        cp16(adst0 + off + 48, asrc + 24);                                     \
        const int kg = (i) * BK + bk;                                          \
        const __half* bsrc = wb + (long)(kg > 0 ? kg - 1 : 0) * FF;            \
        cp16z(bdst0 + off,      bsrc,      kg > 0);                            \
        cp16z(bdst0 + off + 16, bsrc + 8,  kg > 0);                            \
        cp16z(bdst0 + off + 32, bsrc + 16, kg > 0);                            \
        cp16z(bdst0 + off + 48, bsrc + 24, kg > 0);                            \
        cp_commit();                                                           \
    } while (0)

    float acc[4][4][4];
#pragma unroll
    for (int a = 0; a < 4; a++)
#pragma unroll
        for (int b = 0; b < 4; b++)
#pragma unroll
            for (int c = 0; c < 4; c++) acc[a][b][c] = 0.f;

    const int wm = (wid & 1) * 64, wn = (wid >> 1) * 32;
    const int g = lane >> 2, t4 = lane & 3;
    const uint32_t abase = a_lane_base(lane, wm);
    const uint32_t bbase = b_lane_base(lane, wn) + (uint32_t)AS_H * 2u;

    LOAD_STAGE_F(0);

    for (int i = 0; i < NC; i++) {
        cp_wait0();
        __syncthreads();
        if (i + 1 < NC) LOAD_STAGE_F(i + 1);
        const uint32_t soff = sb + (uint32_t)((i & 1) * STG_H) * 2u;
        compute_chunk(soff + abase, soff + bbase, acc);
    }
#undef LOAD_STAGE_F

    // epilogue: add bias matrix, write fp32 out
#pragma unroll
    for (int mf = 0; mf < 4; mf++)
#pragma unroll
        for (int hh = 0; hh < 2; hh++) {
            int m = m0 + wm + mf * 16 + g + hh * 8;
            const long base = ((long)bz * 512 + m) * FF + n0;
#pragma unroll
            for (int nf = 0; nf < 4; nf++) {
                int nc = wn + nf * 8 + t4 * 2;
                float2 bm = *(const float2*)(biasM + base + nc);
                float2 v;
                v.x = acc[mf][nf][hh * 2 + 0] + bm.x;
                v.y = acc[mf][nf][hh * 2 + 1] + bm.y;
                *(float2*)(out + base + nc) = v;
            }
        }
}

// ---------------------------------------------------------------------------
extern "C" void kernel_launch(void* const* d_in, const int* in_sizes, int n_in,
                              void* d_out, int out_size)
{
    const float* x   = (const float*)d_in[0];
    const float* z   = (const float*)d_in[1];
    const float* ww1 = (const float*)d_in[2];
    const float* wb1 = (const float*)d_in[3];
    const float* ww2 = (const float*)d_in[4];
    const float* wb2 = (const float*)d_in[5];
    const float* bw1 = (const float*)d_in[6];
    const float* bb1 = (const float*)d_in[7];
    const float* bw2 = (const float*)d_in[8];
    const float* bb2 = (const float*)d_in[9];
    float* out = (float*)d_out;

    __half *h1w, *h1b, *wts, *xh, *zh, *ww1h, *ww2h, *bw1h, *bw2h;
    float *bias;
    cudaGetSymbolAddress((void**)&h1w,  g_h1w);
    cudaGetSymbolAddress((void**)&h1b,  g_h1b);
    cudaGetSymbolAddress((void**)&wts,  g_wts);
    cudaGetSymbolAddress((void**)&bias, g_bias);
    cudaGetSymbolAddress((void**)&xh,   g_xh);
    cudaGetSymbolAddress((void**)&zh,   g_zh);
    cudaGetSymbolAddress((void**)&ww1h, g_ww1h);
    cudaGetSymbolAddress((void**)&ww2h, g_ww2h);
    cudaGetSymbolAddress((void**)&bw1h, g_bw1h);
    cudaGetSymbolAddress((void**)&bw2h, g_bw2h);

    cudaFuncSetAttribute(mma_gemm<true, true>,
                         cudaFuncAttributeMaxDynamicSharedMemorySize, SMEM_BYTES);
    cudaFuncSetAttribute(mma_gemm<false, true>,
                         cudaFuncAttributeMaxDynamicSharedMemorySize, SMEM_BYTES);
    cudaFuncSetAttribute(mma_gemm<false, false>,
                         cudaFuncAttributeMaxDynamicSharedMemorySize, SMEM_BYTES);
    cudaFuncSetAttribute(mma_final,
                         cudaFuncAttributeMaxDynamicSharedMemorySize, SMEM_BYTES);

    dim3 thr(256);

    // Pre-convert multiplied operands to fp16.
    auto cvt = [&](const float* in, __half* o, long n) {
        int n4 = (int)(n / 4);
        int grid = (n4 + 255) / 256; if (grid > 8192) grid = 8192;
        cvt_f16_kernel<<<grid, 256>>>((const float4*)in, (uint2*)o, n4);
    };
    cvt(x,   xh,   (long)BATCH * 512 * TT);
    cvt(z,   zh,   (long)BATCH * TZv * ZD);
    cvt(ww1, ww1h, 2 * ZD * FF);
    cvt(ww2, ww2h, 2 * FF * FF);
    cvt(bw1, bw1h, 2 * ZD * FF);
    cvt(bw2, bw2h, 2 * FF * FF);

    // weights conv1 + ReLU: M = 8*4097, K = 256  (out: fp16)
    mma_gemm<true, true><<<dim3(FF / BN, (BATCH * T1W + BM - 1) / BM), thr, SMEM_BYTES>>>(
        zh, T1W, ZD, (long)TZv * ZD, ww1h, 2 * ZD, wb1, h1w, BATCH * T1W);

    // bias conv1 + ReLU (truncated): M = 8*513, K = 256  (out: fp16)
    mma_gemm<true, true><<<dim3(FF / BN, (BATCH * T1B + BM - 1) / BM), thr, SMEM_BYTES>>>(
        zh, T1B, ZD, (long)TZv * ZD, bw1h, 2 * ZD, bb1, h1b, BATCH * T1B);

    // weights conv2: M = 8*4096, K = 1024  (out: fp16, B of final GEMM)
    mma_gemm<false, true><<<dim3(FF / BN, (BATCH * TT) / BM), thr, SMEM_BYTES>>>(
        h1w, TT, FF, (long)T1W * FF, ww2h, 2 * FF, wb2, wts, BATCH * TT);

    // bias conv2 (truncated): M = 8*512, K = 1024  (out: fp32, add-only)
    mma_gemm<false, false><<<dim3(FF / BN, (BATCH * 512) / BM), thr, SMEM_BYTES>>>(
        h1b, 512, FF, (long)T1B * FF, bw2h, 2 * FF, bb2, bias, BATCH * 512);

    // final batched GEMM: per-batch 512x512 @ K=4096(shifted) + bias matrix
    mma_final<<<dim3(FF / BN, 512 / BM, BATCH), thr, SMEM_BYTES>>>(xh, wts, bias, out);
}

// round 16
// speedup vs baseline: 1.0012x; 1.0012x over previous
#include <cuda_runtime.h>
#include <cuda_fp16.h>
#include <cstdint>

// ---------------------------------------------------------------------------
// HyperConv via warp-level mma.sync fp16 m16n8k16 (compute_103-safe).
//   out[b,c,f] = sum_{k=1..4095} x[b,c,k] * W[b,k-1,f] + bias[b,c,f]
//   W    = conv2(relu(conv1(z,ww1)+wb1), ww2)+wb2   (T=4096 steps)
//   bias = same with bw*/bb*, only first 512 steps needed
// R14: BK 32->64 (4x fewer iterations), single __syncthreads per iteration
// (wait -> barrier -> load(i+1) -> compute; WAR-safe by barrier placement).
// ---------------------------------------------------------------------------

namespace {
constexpr int BATCH = 8;
constexpr int TT    = 4096;
constexpr int TZv   = 4098;
constexpr int ZD    = 128;
constexpr int FF    = 512;
constexpr int T1W   = 4097;   // hidden steps, weights path
constexpr int T1B   = 513;    // hidden steps, bias path

constexpr int BM = 128, BN = 128, BK = 64;
constexpr int APADH = 72;                // A row stride (halves): 144B -> ldmatrix conflict-free
constexpr int BPADH = 136;               // B row stride (halves): 272B -> ldmatrix conflict-free
constexpr int AS_H = BM * APADH;         // 9216 halves
constexpr int BS_H = BK * BPADH;         // 8704 halves
constexpr int STG_H = AS_H + BS_H;       // 17920 halves = 35840 B / stage
constexpr int SMEM_BYTES = 2 * STG_H * 2;   // 71680 B (2 CTAs/SM)
}

// Scratch (device globals; no allocations allowed). fp16 operand buffers.
__device__ __align__(256) __half g_h1w[BATCH * T1W * FF];   // ~33.5 MB
__device__ __align__(256) __half g_h1b[BATCH * T1B * FF];   // ~4.2 MB
__device__ __align__(256) __half g_wts[BATCH * TT  * FF];   // ~33.5 MB
__device__ __align__(256) float  g_bias[BATCH * 512 * FF];  // ~8.4 MB (fp32, add-only)
__device__ __align__(256) __half g_xh [BATCH * 512 * TT];   // ~33.5 MB
__device__ __align__(256) __half g_zh [BATCH * TZv * ZD];   // ~8.4 MB
__device__ __align__(256) __half g_ww1h[2 * ZD * FF];
__device__ __align__(256) __half g_ww2h[2 * FF * FF];
__device__ __align__(256) __half g_bw1h[2 * ZD * FF];
__device__ __align__(256) __half g_bw2h[2 * FF * FF];

#define DI __device__ __forceinline__

DI uint32_t smem_u32(const void* p) {
    uint32_t a;
    asm("{ .reg .u64 t; cvta.to.shared.u64 t, %1; cvt.u32.u64 %0, t; }"
        : "=r"(a) : "l"(p));
    return a;
}
DI void cp16(uint32_t dst, const void* src) {
    asm volatile("cp.async.cg.shared.global [%0], [%1], 16;"
                 :: "r"(dst), "l"(src));
}
DI void cp16z(uint32_t dst, const void* src, int valid) {  // zero-fill if !valid
    asm volatile("cp.async.cg.shared.global [%0], [%1], 16, %2;"
                 :: "r"(dst), "l"(src), "r"(valid ? 16 : 0));
}
DI void cp_commit() { asm volatile("cp.async.commit_group;"); }
DI void cp_wait0()  { asm volatile("cp.async.wait_group 0;"); }

DI void ldsm_x4(uint32_t& r0, uint32_t& r1, uint32_t& r2, uint32_t& r3, uint32_t a) {
    asm volatile("ldmatrix.sync.aligned.m8n8.x4.shared.b16 {%0,%1,%2,%3}, [%4];"
                 : "=r"(r0), "=r"(r1), "=r"(r2), "=r"(r3) : "r"(a));
}
DI void ldsm_x4t(uint32_t& r0, uint32_t& r1, uint32_t& r2, uint32_t& r3, uint32_t a) {
    asm volatile("ldmatrix.sync.aligned.m8n8.x4.trans.shared.b16 {%0,%1,%2,%3}, [%4];"
                 : "=r"(r0), "=r"(r1), "=r"(r2), "=r"(r3) : "r"(a));
}
DI void mma16(float c[4], const uint32_t a[4], uint32_t b0, uint32_t b1) {
    asm volatile(
        "mma.sync.aligned.m16n8k16.row.col.f32.f16.f16.f32 "
        "{%0,%1,%2,%3}, {%4,%5,%6,%7}, {%8,%9}, {%0,%1,%2,%3};"
        : "+f"(c[0]), "+f"(c[1]), "+f"(c[2]), "+f"(c[3])
        : "r"(a[0]), "r"(a[1]), "r"(a[2]), "r"(a[3]), "r"(b0), "r"(b1));
}

// Per-lane ldmatrix base offsets (bytes) within a stage.
// A [m][k] halves, row stride APADH. x4: lanes 0-7 rows m+0..7 @k0,
// 8-15 rows m+8..15 @k0, 16-23 rows m+0..7 @k+8, 24-31 rows m+8..15 @k+8.
DI uint32_t a_lane_base(int lane, int wm) {
    int row = wm + (lane & 7) + ((lane >> 3) & 1) * 8;
    int col = ((lane >> 4) & 1) * 8;
    return (uint32_t)(row * APADH + col) * 2u;
}
// B [k][n] halves, row stride BPADH. x4.trans: lanes 0-7 rows k+0..7 @n0,
// 8-15 rows k+8..15 @n0, 16-23 rows k+0..7 @n+8, 24-31 rows k+8..15 @n+8.
DI uint32_t b_lane_base(int lane, int wn) {
    int row = (lane & 7) + ((lane >> 3) & 1) * 8;
    int col = wn + ((lane >> 4) & 1) * 8;
    return (uint32_t)(row * BPADH + col) * 2u;
}

// Load fragments for one k16 step (ks in 0..3 within a BK=64 chunk).
DI void load_frags(uint32_t a_sb, uint32_t b_sb, int ks,
                   uint32_t af[4][4], uint32_t bq[2][4]) {
    const uint32_t ak = a_sb + (uint32_t)(ks * 16) * 2u;
    const uint32_t bk = b_sb + (uint32_t)(ks * 16 * BPADH) * 2u;
#pragma unroll
    for (int mf = 0; mf < 4; mf++)
        ldsm_x4(af[mf][0], af[mf][1], af[mf][2], af[mf][3],
                ak + (uint32_t)(mf * 16 * APADH) * 2u);
#pragma unroll
    for (int nfp = 0; nfp < 2; nfp++)
        ldsm_x4t(bq[nfp][0], bq[nfp][1], bq[nfp][2], bq[nfp][3],
                 bk + (uint32_t)(nfp * 16) * 2u);
}

// One BK=64 chunk: 4 k16 steps, double-buffered fragments.
DI void compute_chunk(uint32_t a_sb, uint32_t b_sb, float acc[4][4][4]) {
    uint32_t af[2][4][4], bq[2][2][4];
    load_frags(a_sb, b_sb, 0, af[0], bq[0]);
#pragma unroll
    for (int ks = 0; ks < 4; ks++) {
        const int cur = ks & 1;
        if (ks < 3) load_frags(a_sb, b_sb, ks + 1, af[cur ^ 1], bq[cur ^ 1]);
#pragma unroll
        for (int mf = 0; mf < 4; mf++)
#pragma unroll
            for (int nf = 0; nf < 4; nf++)
                mma16(acc[mf][nf], af[cur][mf],
                      bq[cur][nf >> 1][(nf & 1) * 2],
                      bq[cur][nf >> 1][(nf & 1) * 2 + 1]);
    }
}

// Elementwise fp32 -> fp16 converter (grid-stride, float4 -> half4).
__global__ void cvt_f16_kernel(const float4* __restrict__ in,
                               uint2* __restrict__ out, int n4) {
    for (int i = blockIdx.x * blockDim.x + threadIdx.x; i < n4;
         i += gridDim.x * blockDim.x) {
        float4 v = in[i];
        __half2 lo = __floats2half2_rn(v.x, v.y);
        __half2 hi = __floats2half2_rn(v.z, v.w);
        uint2 o;
        o.x = *(uint32_t*)&lo; o.y = *(uint32_t*)&hi;
        out[i] = o;
    }
}

// ---------------------------------------------------------------------------
// mma_gemm: C[m, n0:n0+128] = A_row(m)[0:K] @ W[K,512] + biasVec
// A_row(m) = A + b*batchStride + t*rowStride (halves), m = b*rowsPerBatch + t.
// OUTH: write fp16; else fp32.
// ---------------------------------------------------------------------------
template<bool RELU, bool OUTH>
__global__ void __launch_bounds__(256, 2) mma_gemm(
    const __half* __restrict__ A, int rowsPerBatch, int rowStride, long batchStride,
    const __half* __restrict__ W, int K,
    const float* __restrict__ biasVec, void* __restrict__ Cv, int M)
{
    extern __shared__ __half smh[];
    const uint32_t sb = smem_u32(smh);
    const int tid = threadIdx.x, lane = tid & 31, wid = tid >> 5;
    const int m0 = blockIdx.y * BM, n0 = blockIdx.x * BN;

    // A gmem mapping: row am = tid>>1 (0..127), half-chunk ah = (tid&1)*32 halves
    const int am = tid >> 1, ah = (tid & 1) * 32;
    const __half* aptr;
    {
        int mm = m0 + am; if (mm >= M) mm = M - 1;   // clamp; store guarded
        int b = mm / rowsPerBatch, t = mm - b * rowsPerBatch;
        aptr = A + (long)b * batchStride + (long)t * rowStride + ah;
    }
    const uint32_t adst0 = sb + (uint32_t)(am * APADH + ah) * 2u;

    // B gmem mapping: k-row bk = tid>>2 (0..63), n-chunk bn = (tid&3)*32 halves
    const int bk = tid >> 2, bn = (tid & 3) * 32;
    const __half* bptr = W + (long)bk * FF + n0 + bn;
    const uint32_t bdst0 = sb + (uint32_t)(AS_H + bk * BPADH + bn) * 2u;

    const int NC = K / BK;

#define LOAD_STAGE(i)                                                          \
    do {                                                                       \
        const uint32_t off = (uint32_t)(((i) & 1) * STG_H) * 2u;               \
        const __half* asrc = aptr + (i) * BK;                                  \
        cp16(adst0 + off,      asrc);                                          \
        cp16(adst0 + off + 16, asrc + 8);                                      \
        cp16(adst0 + off + 32, asrc + 16);                                     \
        cp16(adst0 + off + 48, asrc + 24);                                     \
        const __half* bsrc = bptr + (long)(i) * BK * FF;                       \
        cp16(bdst0 + off,      bsrc);                                          \
        cp16(bdst0 + off + 16, bsrc + 8);                                      \
        cp16(bdst0 + off + 32, bsrc + 16);                                     \
        cp16(bdst0 + off + 48, bsrc + 24);                                     \
        cp_commit();                                                           \
    } while (0)

    float acc[4][4][4];
#pragma unroll
    for (int a = 0; a < 4; a++)
#pragma unroll
        for (int b = 0; b < 4; b++)
#pragma unroll
            for (int c = 0; c < 4; c++) acc[a][b][c] = 0.f;

    const int wm = (wid & 1) * 64, wn = (wid >> 1) * 32;
    const int g = lane >> 2, t4 = lane & 3;
    const uint32_t abase = a_lane_base(lane, wm);
    const uint32_t bbase = b_lane_base(lane, wn) + (uint32_t)AS_H * 2u;

    LOAD_STAGE(0);

    for (int i = 0; i < NC; i++) {
        cp_wait0();                 // stage i fully in SMEM
        __syncthreads();            // all warps done with buffer (i-1)&1
        if (i + 1 < NC) LOAD_STAGE(i + 1);   // overwrites (i+1)&1 = (i-1)&1: safe
        const uint32_t soff = sb + (uint32_t)((i & 1) * STG_H) * 2u;
        compute_chunk(soff + abase, soff + bbase, acc);
    }
#undef LOAD_STAGE

    // epilogue (c frag: m = g(+8), n = t4*2(+1))
    float bv[4][2];
#pragma unroll
    for (int nf = 0; nf < 4; nf++) {
        int nc = n0 + wn + nf * 8 + t4 * 2;
        bv[nf][0] = biasVec[nc]; bv[nf][1] = biasVec[nc + 1];
    }
#pragma unroll
    for (int mf = 0; mf < 4; mf++)
#pragma unroll
        for (int hh = 0; hh < 2; hh++) {
            int m = m0 + wm + mf * 16 + g + hh * 8;
            if (m < M) {
#pragma unroll
                for (int nf = 0; nf < 4; nf++) {
                    float vx = acc[mf][nf][hh * 2 + 0] + bv[nf][0];
                    float vy = acc[mf][nf][hh * 2 + 1] + bv[nf][1];
                    if (RELU) { vx = fmaxf(vx, 0.f); vy = fmaxf(vy, 0.f); }
                    long idx = (long)m * FF + n0 + wn + nf * 8 + t4 * 2;
                    if (OUTH) {
                        __half2 h = __floats2half2_rn(vx, vy);
                        *(__half2*)((__half*)Cv + idx) = h;
                    } else {
                        float2 v; v.x = vx; v.y = vy;
                        *(float2*)((float*)Cv + idx) = v;
                    }
                }
            }
        }
}

// ---------------------------------------------------------------------------
// mma_final: out[b,m,n] = sum_{k=1..4095} x[b,m,k]*wts[b,k-1,n] + biasM[b,m,n]
// A = fp16 x, B row kg reads wts[kg-1]; kg==0 zero-filled.
// grid = (4 n-tiles, 4 m-tiles, 8 batches), K=4096 -> 64 chunks.
// ---------------------------------------------------------------------------
__global__ void __launch_bounds__(256, 2) mma_final(
    const __half* __restrict__ x, const __half* __restrict__ wts,
    const float* __restrict__ biasM, float* __restrict__ out)
{
    extern __shared__ __half smh[];
    const uint32_t sb = smem_u32(smh);
    const int tid = threadIdx.x, lane = tid & 31, wid = tid >> 5;
    const int bz = blockIdx.z;
    const int m0 = blockIdx.y * BM, n0 = blockIdx.x * BN;

    const int am = tid >> 1, ah = (tid & 1) * 32;
    const __half* aptr = x + (long)(bz * 512 + m0 + am) * TT + ah;
    const uint32_t adst0 = sb + (uint32_t)(am * APADH + ah) * 2u;

    const int bk = tid >> 2, bn = (tid & 3) * 32;
    const __half* wb = wts + (long)bz * TT * FF + n0 + bn;
    const uint32_t bdst0 = sb + (uint32_t)(AS_H + bk * BPADH + bn) * 2u;

    const int NC = TT / BK;   // 64

#define LOAD_STAGE_F(i)                                                        \
    do {                                                                       \
        const uint32_t off = (uint32_t)(((i) & 1) * STG_H) * 2u;               \
        const __half* asrc = aptr + (i) * BK;                                  \
        cp16(adst0 + off,      asrc);                                          \
        cp16(adst0 + off + 16, asrc + 8);                                      \
        cp16(adst0 + off + 32, asrc + 16);                                     \
        cp16(adst0 + off + 48, asrc + 24);                                     \
        const int kg = (i) * BK + bk;                                          \
        const __half* bsrc = wb + (long)(kg > 0 ? kg - 1 : 0) * FF;            \
        cp16z(bdst0 + off,      bsrc,      kg > 0);                            \
        cp16z(bdst0 + off + 16, bsrc + 8,  kg > 0);                            \
        cp16z(bdst0 + off + 32, bsrc + 16, kg > 0);                            \
        cp16z(bdst0 + off + 48, bsrc + 24, kg > 0);                            \
        cp_commit();                                                           \
    } while (0)

    float acc[4][4][4];
#pragma unroll
    for (int a = 0; a < 4; a++)
#pragma unroll
        for (int b = 0; b < 4; b++)
#pragma unroll
            for (int c = 0; c < 4; c++) acc[a][b][c] = 0.f;

    const int wm = (wid & 1) * 64, wn = (wid >> 1) * 32;
    const int g = lane >> 2, t4 = lane & 3;
    const uint32_t abase = a_lane_base(lane, wm);
    const uint32_t bbase = b_lane_base(lane, wn) + (uint32_t)AS_H * 2u;

    LOAD_STAGE_F(0);

    for (int i = 0; i < NC; i++) {
        cp_wait0();
        __syncthreads();
        if (i + 1 < NC) LOAD_STAGE_F(i + 1);
        const uint32_t soff = sb + (uint32_t)((i & 1) * STG_H) * 2u;
        compute_chunk(soff + abase, soff + bbase, acc);
    }
#undef LOAD_STAGE_F

    // epilogue: add bias matrix, write fp32 out
#pragma unroll
    for (int mf = 0; mf < 4; mf++)
#pragma unroll
        for (int hh = 0; hh < 2; hh++) {
            int m = m0 + wm + mf * 16 + g + hh * 8;
            const long base = ((long)bz * 512 + m) * FF + n0;
#pragma unroll
            for (int nf = 0; nf < 4; nf++) {
                int nc = wn + nf * 8 + t4 * 2;
                float2 bm = *(const float2*)(biasM + base + nc);
                float2 v;
                v.x = acc[mf][nf][hh * 2 + 0] + bm.x;
                v.y = acc[mf][nf][hh * 2 + 1] + bm.y;
                *(float2*)(out + base + nc) = v;
            }
        }
}

// ---------------------------------------------------------------------------
extern "C" void kernel_launch(void* const* d_in, const int* in_sizes, int n_in,
                              void* d_out, int out_size)
{
    const float* x   = (const float*)d_in[0];
    const float* z   = (const float*)d_in[1];
    const float* ww1 = (const float*)d_in[2];
    const float* wb1 = (const float*)d_in[3];
    const float* ww2 = (const float*)d_in[4];
    const float* wb2 = (const float*)d_in[5];
    const float* bw1 = (const float*)d_in[6];
    const float* bb1 = (const float*)d_in[7];
    const float* bw2 = (const float*)d_in[8];
    const float* bb2 = (const float*)d_in[9];
    float* out = (float*)d_out;

    __half *h1w, *h1b, *wts, *xh, *zh, *ww1h, *ww2h, *bw1h, *bw2h;
    float *bias;
    cudaGetSymbolAddress((void**)&h1w,  g_h1w);
    cudaGetSymbolAddress((void**)&h1b,  g_h1b);
    cudaGetSymbolAddress((void**)&wts,  g_wts);
    cudaGetSymbolAddress((void**)&bias, g_bias);
    cudaGetSymbolAddress((void**)&xh,   g_xh);
    cudaGetSymbolAddress((void**)&zh,   g_zh);
    cudaGetSymbolAddress((void**)&ww1h, g_ww1h);
    cudaGetSymbolAddress((void**)&ww2h, g_ww2h);
    cudaGetSymbolAddress((void**)&bw1h, g_bw1h);
    cudaGetSymbolAddress((void**)&bw2h, g_bw2h);

    cudaFuncSetAttribute(mma_gemm<true, true>,
                         cudaFuncAttributeMaxDynamicSharedMemorySize, SMEM_BYTES);
    cudaFuncSetAttribute(mma_gemm<false, true>,
                         cudaFuncAttributeMaxDynamicSharedMemorySize, SMEM_BYTES);
    cudaFuncSetAttribute(mma_gemm<false, false>,
                         cudaFuncAttributeMaxDynamicSharedMemorySize, SMEM_BYTES);
    cudaFuncSetAttribute(mma_final,
                         cudaFuncAttributeMaxDynamicSharedMemorySize, SMEM_BYTES);

    dim3 thr(256);

    // Pre-convert multiplied operands to fp16.
    auto cvt = [&](const float* in, __half* o, long n) {
        int n4 = (int)(n / 4);
        int grid = (n4 + 255) / 256; if (grid > 8192) grid = 8192;
        cvt_f16_kernel<<<grid, 256>>>((const float4*)in, (uint2*)o, n4);
    };
    cvt(x,   xh,   (long)BATCH * 512 * TT);
    cvt(z,   zh,   (long)BATCH * TZv * ZD);
    cvt(ww1, ww1h, 2 * ZD * FF);
    cvt(ww2, ww2h, 2 * FF * FF);
    cvt(bw1, bw1h, 2 * ZD * FF);
    cvt(bw2, bw2h, 2 * FF * FF);

    // weights conv1 + ReLU: M = 8*4097, K = 256  (out: fp16)
    mma_gemm<true, true><<<dim3(FF / BN, (BATCH * T1W + BM - 1) / BM), thr, SMEM_BYTES>>>(
        zh, T1W, ZD, (long)TZv * ZD, ww1h, 2 * ZD, wb1, h1w, BATCH * T1W);

    // bias conv1 + ReLU (truncated): M = 8*513, K = 256  (out: fp16)
    mma_gemm<true, true><<<dim3(FF / BN, (BATCH * T1B + BM - 1) / BM), thr, SMEM_BYTES>>>(
        zh, T1B, ZD, (long)TZv * ZD, bw1h, 2 * ZD, bb1, h1b, BATCH * T1B);

    // weights conv2: M = 8*4096, K = 1024  (out: fp16, B of final GEMM)
    mma_gemm<false, true><<<dim3(FF / BN, (BATCH * TT) / BM), thr, SMEM_BYTES>>>(
        h1w, TT, FF, (long)T1W * FF, ww2h, 2 * FF, wb2, wts, BATCH * TT);

    // bias conv2 (truncated): M = 8*512, K = 1024  (out: fp32, add-only)
    mma_gemm<false, false><<<dim3(FF / BN, (BATCH * 512) / BM), thr, SMEM_BYTES>>>(
        h1b, 512, FF, (long)T1B * FF, bw2h, 2 * FF, bb2, bias, BATCH * 512);

    // final batched GEMM: per-batch 512x512 @ K=4096(shifted) + bias matrix
    mma_final<<<dim3(FF / BN, 512 / BM, BATCH), thr, SMEM_BYTES>>>(xh, wts, bias, out);
}